// round 5
// baseline (speedup 1.0000x reference)
#include <cuda_runtime.h>
#include <cstdint>
#include <cstddef>

#define T_N   1024
#define B_N   64
#define V_N   32000
#define H_N   512

#define GC    32                 // col-members per group
#define GB    4                  // independent batch-groups
#define GRID_R (GC * GB)         // 128 CTAs
#define BPG   16                 // batches per group
#define CPM   16                 // cols per member
#define NTHR  256

// ---------------- persistent device scratch ----------------
__device__ float    g_embW0[(size_t)V_N * H_N];   // emb @ Wih0^T + bih0 + bhh0
__device__ float    g_h0[2][B_N * H_N];
__device__ float    g_h1[2][B_N * H_N];
__device__ unsigned g_flag0[GRID_R * 8];          // early (h0) flags, 32B stride
__device__ unsigned g_flag1[GRID_R * 8];          // late  (h1) flags

// ---------------- reset: deterministic per launch / graph replay ----------------
__global__ void reset_kernel() {
    int i = blockIdx.x * blockDim.x + threadIdx.x;
    if (i < B_N * H_N) {
        g_h0[0][i] = 0.f; g_h0[1][i] = 0.f;
        g_h1[0][i] = 0.f; g_h1[1][i] = 0.f;
    }
    if (i < GRID_R * 8) { g_flag0[i] = 0u; g_flag1[i] = 0u; }
}

// ---------------- embW0[v][h] = emb[v]·Wih0[h] + bih0[h] + bhh0[h] ----------------
__global__ __launch_bounds__(256) void embw_kernel(const float* __restrict__ A,
                                                   const float* __restrict__ W,
                                                   const float* __restrict__ bih,
                                                   const float* __restrict__ bhh) {
    __shared__ float As[8][132];
    __shared__ float Ws[8][132];
    const int tid   = threadIdx.x;
    const int hBase = blockIdx.x * 128;
    const int vBase = blockIdx.y * 128;
    const int lRow  = tid >> 1;
    const int lCol  = (tid & 1) * 4;
    const int tx    = tid & 15;
    const int ty    = tid >> 4;

    const float4* Ap = (const float4*)(A + (size_t)(vBase + lRow) * H_N + lCol);
    const float4* Wp = (const float4*)(W + (size_t)(hBase + lRow) * H_N + lCol);

    float acc[8][8];
#pragma unroll
    for (int i = 0; i < 8; i++)
#pragma unroll
        for (int j = 0; j < 8; j++) acc[i][j] = 0.f;

    float4 av = Ap[0];
    float4 wv = Wp[0];

    for (int k0 = 0; k0 < 512; k0 += 8) {
        __syncthreads();
        As[lCol + 0][lRow] = av.x; As[lCol + 1][lRow] = av.y;
        As[lCol + 2][lRow] = av.z; As[lCol + 3][lRow] = av.w;
        Ws[lCol + 0][lRow] = wv.x; Ws[lCol + 1][lRow] = wv.y;
        Ws[lCol + 2][lRow] = wv.z; Ws[lCol + 3][lRow] = wv.w;
        __syncthreads();
        if (k0 + 8 < 512) {
            av = Ap[(k0 + 8) >> 2];
            wv = Wp[(k0 + 8) >> 2];
        }
#pragma unroll
        for (int k = 0; k < 8; k++) {
            float a[8], w[8];
            *(float4*)&a[0] = *(const float4*)&As[k][ty * 8];
            *(float4*)&a[4] = *(const float4*)&As[k][ty * 8 + 4];
            *(float4*)&w[0] = *(const float4*)&Ws[k][tx * 8];
            *(float4*)&w[4] = *(const float4*)&Ws[k][tx * 8 + 4];
#pragma unroll
            for (int i = 0; i < 8; i++)
#pragma unroll
                for (int j = 0; j < 8; j++) acc[i][j] += a[i] * w[j];
        }
    }

#pragma unroll
    for (int i = 0; i < 8; i++) {
        const int v = vBase + ty * 8 + i;
        float* orow = &g_embW0[(size_t)v * H_N + hBase + tx * 8];
        float o[8];
#pragma unroll
        for (int j = 0; j < 8; j++) {
            int h = hBase + tx * 8 + j;
            o[j] = acc[i][j] + __ldg(&bih[h]) + __ldg(&bhh[h]);
        }
        *(float4*)&orow[0] = *(float4*)&o[0];
        *(float4*)&orow[4] = *(float4*)&o[4];
    }
}

// ---------------- packed-fp32 helpers ----------------
typedef unsigned long long u64;
__device__ __forceinline__ u64 ffma2(u64 a, u64 b, u64 c) {
    u64 d;
    asm("fma.rn.f32x2 %0, %1, %2, %3;" : "=l"(d) : "l"(a), "l"(b), "l"(c));
    return d;
}
__device__ __forceinline__ float unpack_sum(u64 a) {
    float lo, hi;
    asm("mov.b64 {%0, %1}, %2;" : "=f"(lo), "=f"(hi) : "l"(a));
    return lo + hi;
}

// ---------------- persistent recurrence kernel ----------------
// SMEM floats: W0[8192] WA[8192] WB[8192] Hs0[8192] Hs1[8192] Rs0[4352] Rs1[4352] b1[16]
#define OFF_W0 0
#define OFF_WA 8192
#define OFF_WB 16384
#define OFF_H0 24576
#define OFF_H1 32768
#define OFF_R0 40960
#define OFF_R1 (OFF_R0 + 4352)
#define OFF_B1 (OFF_R1 + 4352)
#define SMEM_FLOATS (OFF_B1 + 16)
#define SMEM_BYTES  (SMEM_FLOATS * 4)

__global__ __launch_bounds__(NTHR, 1) void rnn_kernel(const int*   __restrict__ input,
                                                      const float* __restrict__ Whh0,
                                                      const float* __restrict__ Wih1,
                                                      const float* __restrict__ Whh1,
                                                      const float* __restrict__ bih1,
                                                      const float* __restrict__ bhh1,
                                                      float*       __restrict__ out) {
    extern __shared__ float smem[];
    float* W0s = smem + OFF_W0;
    float* WAs = smem + OFF_WA;
    float* WBs = smem + OFF_WB;
    float* Hs0 = smem + OFF_H0;
    float* Hs1 = smem + OFF_H1;
    float* Rs0 = smem + OFF_R0;
    float* Rs1 = smem + OFF_R1;
    float* b1s = smem + OFF_B1;

    const int tid  = threadIdx.x;
    const int cid  = blockIdx.x;
    const int m    = cid & (GC - 1);   // member: cols [m*16, m*16+16)
    const int grp  = cid >> 5;         // group: batches [grp*16, grp*16+16)
    const int gb16 = grp * BPG;
    const int w    = tid >> 5;
    const int lane = tid & 31;
    const int o    = w >> 2;           // batch-oct (0..1)
    const int cc   = w & 3;            // col-quad  (0..3)

    // ---- preload weight slices ----
    {
        const float4* s0 = (const float4*)Whh0 + (size_t)m * 2048;
        const float4* s1 = (const float4*)Wih1 + (size_t)m * 2048;
        const float4* s2 = (const float4*)Whh1 + (size_t)m * 2048;
        float4* d0 = (float4*)W0s; float4* d1 = (float4*)WAs; float4* d2 = (float4*)WBs;
        for (int r = tid; r < 2048; r += NTHR) {
            d0[r] = __ldg(&s0[r]);
            d1[r] = __ldg(&s1[r]);
            d2[r] = __ldg(&s2[r]);
        }
        if (tid < CPM) b1s[tid] = __ldg(&bih1[m * CPM + tid]) + __ldg(&bhh1[m * CPM + tid]);
    }
    __syncthreads();

    // output decode: thread tid owns Rs row tid
    const int w_o    = tid >> 5;
    const int i_o    = (tid >> 2) & 7;
    const int c_o    = tid & 3;
    const int b_out  = gb16 + (w_o >> 2) * 8 + i_o;
    const int c_loc  = (w_o & 3) * 4 + c_o;
    const int c_glob = m * CPM + c_loc;

    const ulonglong2* W0u = (const ulonglong2*)W0s;
    const ulonglong2* WAu = (const ulonglong2*)WAs;
    const ulonglong2* WBu = (const ulonglong2*)WBs;
    const ulonglong2* H0u = (const ulonglong2*)Hs0;
    const ulonglong2* H1u = (const ulonglong2*)Hs1;
    const unsigned sd0 = (unsigned)__cvta_generic_to_shared(Hs0);
    const unsigned sd1 = (unsigned)__cvta_generic_to_shared(Hs1);

    u64 acc[8][4];

    // mma sub-chunk: k-quarter J on (Wm, Hm) -> acc
#define MMA_CHUNK(Wm, Hm, J)                                                     \
    {                                                                            \
        ulonglong2 wq[4];                                                        \
        _Pragma("unroll")                                                        \
        for (int c = 0; c < 4; c++) wq[c] = (Wm)[(cc * 4 + c) * 128 + (J) * 32 + lane]; \
        _Pragma("unroll")                                                        \
        for (int i = 0; i < 8; i++) {                                            \
            ulonglong2 hv = (Hm)[((J) >> 1) * 1024 + (o * 8 + i) * 64 + ((J) & 1) * 32 + lane]; \
            _Pragma("unroll")                                                    \
            for (int c = 0; c < 4; c++) {                                        \
                acc[i][c] = ffma2(hv.x, wq[c].x, acc[i][c]);                     \
                acc[i][c] = ffma2(hv.y, wq[c].y, acc[i][c]);                     \
            }                                                                    \
        }                                                                        \
    }

#define ZERO_ACC()                                                               \
    _Pragma("unroll")                                                            \
    for (int i = 0; i < 8; i++)                                                  \
        _Pragma("unroll")                                                        \
        for (int c = 0; c < 4; c++) acc[i][c] = 0ull;

    // shfl pre-reduce acc -> Rs (lanes 0..15 write rows of 16, stride 17)
#define REDUCE_TO(RS)                                                            \
    _Pragma("unroll")                                                            \
    for (int i = 0; i < 8; i++)                                                  \
        _Pragma("unroll")                                                        \
        for (int c = 0; c < 4; c++) {                                            \
            float v = unpack_sum(acc[i][c]);                                     \
            v += __shfl_xor_sync(0xffffffffu, v, 16);                            \
            if (lane < 16) (RS)[(w * 32 + i * 4 + c) * 17 + lane] = v;           \
        }

    // stage one k-half (q) of a 16-row state block into SMEM (4 cp.async/thread)
#define STAGE_HALF(SD, SRC, Q)                                                   \
    {                                                                            \
        _Pragma("unroll")                                                        \
        for (int r = 0; r < 4; r++) {                                            \
            int l   = r * NTHR + tid;                                            \
            int b_l = l >> 6;                                                    \
            int c4  = l & 63;                                                    \
            size_t srcf4 = (size_t)(gb16 + b_l) * 128 + (Q) * 64 + c4;           \
            asm volatile("cp.async.cg.shared.global [%0], [%1], 16;\n"           \
                         :: "r"((SD) + ((Q) * 1024 + l) * 16), "l"((SRC) + srcf4 * 4)); \
        }                                                                        \
        asm volatile("cp.async.commit_group;\n");                                \
    }

    for (int s = 1; s <= T_N + 1; s++) {
        // ---- independent gather for h0 epilogue ----
        float xw = 0.f;
        if (s <= T_N) {
            int tok = __ldg(&input[(s - 1) * B_N + b_out]);
            xw = __ldcg(&g_embW0[(size_t)tok * H_N + c_glob]);
        }

        // ---- A: wait early flags (peers' h0[s-1] published) ----
        if (w == 0) {
            const unsigned* fp = &g_flag0[(grp * GC + lane) * 8];
            unsigned v;
            do {
                asm volatile("ld.relaxed.gpu.global.u32 %0, [%1];"
                             : "=r"(v) : "l"(fp) : "memory");
            } while (__any_sync(0xffffffffu, v < (unsigned)(s - 1)));
            __threadfence();
        }
        __syncthreads();

        // ---- B: stage h0[s-2] (2 commit groups) ----
        {
            const float* src = g_h0[s & 1];
            STAGE_HALF(sd0, src, 0)
            STAGE_HALF(sd0, src, 1)
        }

        // ---- D: pass 1a — Whh0 · h0[s-2] ----
        ZERO_ACC()
        asm volatile("cp.async.wait_group 1;\n" ::: "memory");
        __syncthreads();
        MMA_CHUNK(W0u, H0u, 0)
        MMA_CHUNK(W0u, H0u, 1)
        asm volatile("cp.async.wait_group 0;\n" ::: "memory");
        __syncthreads();
        MMA_CHUNK(W0u, H0u, 2)
        MMA_CHUNK(W0u, H0u, 3)

        // ---- E: reduce0 + h0 store + early flag ----
        REDUCE_TO(Rs0)
        __syncthreads();
        {
            float ssum = 0.f;
#pragma unroll
            for (int l = 0; l < 16; l++) ssum += Rs0[tid * 17 + l];
            if (s <= T_N)
                __stcg(&g_h0[(s - 1) & 1][b_out * H_N + c_glob], tanhf(ssum + xw));
        }
        __syncthreads();
        if (tid == 0) {
            __threadfence();
            asm volatile("st.relaxed.gpu.global.u32 [%0], %1;"
                         :: "l"(&g_flag0[cid * 8]), "r"((unsigned)s) : "memory");
        }

        // ---- F: wait late flags (peers' h1[s-3]) then stage h1 ----
        if (w == 0) {
            const unsigned* fp = &g_flag1[(grp * GC + lane) * 8];
            unsigned v;
            do {
                asm volatile("ld.relaxed.gpu.global.u32 %0, [%1];"
                             : "=r"(v) : "l"(fp) : "memory");
            } while (__any_sync(0xffffffffu, v < (unsigned)(s - 1)));
            __threadfence();
        }
        __syncthreads();
        {
            const float* src = g_h1[(s + 1) & 1];
            STAGE_HALF(sd1, src, 0)
            STAGE_HALF(sd1, src, 1)
        }

        // ---- G: pass 1b — Wih1 · h0[s-2] (re-read Hs0; overlaps h1 staging) ----
        ZERO_ACC()
        MMA_CHUNK(WAu, H0u, 0)
        MMA_CHUNK(WAu, H0u, 1)
        MMA_CHUNK(WAu, H0u, 2)
        MMA_CHUNK(WAu, H0u, 3)

        // ---- H: pass 2 — Whh1 · h1[s-3] accumulated on top ----
        asm volatile("cp.async.wait_group 1;\n" ::: "memory");
        __syncthreads();
        MMA_CHUNK(WBu, H1u, 0)
        MMA_CHUNK(WBu, H1u, 1)
        asm volatile("cp.async.wait_group 0;\n" ::: "memory");
        __syncthreads();
        MMA_CHUNK(WBu, H1u, 2)
        MMA_CHUNK(WBu, H1u, 3)

        // ---- I: reduce1 + h1 store + late flag ----
        REDUCE_TO(Rs1)
        __syncthreads();
        {
            float ssum = 0.f;
#pragma unroll
            for (int l = 0; l < 16; l++) ssum += Rs1[tid * 17 + l];
            if (s >= 2) {
                float v = tanhf(ssum + b1s[c_loc]);
                __stcg(&g_h1[s & 1][b_out * H_N + c_glob], v);
                if (s == T_N + 1) __stcg(&out[b_out * H_N + c_glob], v);
            }
        }
        __syncthreads();
        if (tid == 0) {
            __threadfence();
            asm volatile("st.relaxed.gpu.global.u32 [%0], %1;"
                         :: "l"(&g_flag1[cid * 8]), "r"((unsigned)s) : "memory");
        }
    }
#undef MMA_CHUNK
#undef ZERO_ACC
#undef REDUCE_TO
#undef STAGE_HALF
}

// ---------------- launch ----------------
extern "C" void kernel_launch(void* const* d_in, const int* in_sizes, int n_in,
                              void* d_out, int out_size) {
    const int*   input = (const int*)  d_in[0];
    const float* emb   = (const float*)d_in[1];
    const float* Wih0  = (const float*)d_in[2];
    const float* Whh0  = (const float*)d_in[3];
    const float* bih0  = (const float*)d_in[4];
    const float* bhh0  = (const float*)d_in[5];
    const float* Wih1  = (const float*)d_in[6];
    const float* Whh1  = (const float*)d_in[7];
    const float* bih1  = (const float*)d_in[8];
    const float* bhh1  = (const float*)d_in[9];
    float* out = (float*)d_out;

    cudaFuncSetAttribute(rnn_kernel, cudaFuncAttributeMaxDynamicSharedMemorySize, SMEM_BYTES);

    reset_kernel<<<(B_N * H_N + 255) / 256, 256>>>();
    embw_kernel<<<dim3(H_N / 128, V_N / 128), 256>>>(emb, Wih0, bih0, bhh0);
    rnn_kernel<<<GRID_R, NTHR, SMEM_BYTES>>>(input, Whh0, Wih1, Whh1, bih1, bhh1, out);
}

// round 6
// speedup vs baseline: 1.0712x; 1.0712x over previous
#include <cuda_runtime.h>
#include <cstdint>
#include <cstddef>

#define T_N   1024
#define B_N   64
#define V_N   32000
#define H_N   512

#define GC    32                 // col-members per group
#define GB    4                  // independent batch-groups
#define GRID_R (GC * GB)         // 128 CTAs
#define BPG   16                 // batches per group
#define CPM   16                 // cols per member
#define NTHR  256

// ---------------- persistent device scratch ----------------
__device__ float    g_embW0[(size_t)V_N * H_N];   // emb @ Wih0^T + bih0 + bhh0
__device__ float    g_h0[2][B_N * H_N];
__device__ float    g_h1[2][B_N * H_N];
__device__ unsigned g_flag[GRID_R * 8];           // per-CTA step flags (32B stride)

// ---------------- reset: deterministic per launch / graph replay ----------------
__global__ void reset_kernel() {
    int i = blockIdx.x * blockDim.x + threadIdx.x;
    if (i < B_N * H_N) {
        g_h0[0][i] = 0.f; g_h0[1][i] = 0.f;
        g_h1[0][i] = 0.f; g_h1[1][i] = 0.f;
    }
    if (i < GRID_R * 8) g_flag[i] = 0u;
}

// ---------------- embW0[v][h] = emb[v]·Wih0[h] + bih0[h] + bhh0[h] ----------------
__global__ __launch_bounds__(256) void embw_kernel(const float* __restrict__ A,
                                                   const float* __restrict__ W,
                                                   const float* __restrict__ bih,
                                                   const float* __restrict__ bhh) {
    __shared__ float As[8][132];
    __shared__ float Ws[8][132];
    const int tid   = threadIdx.x;
    const int hBase = blockIdx.x * 128;
    const int vBase = blockIdx.y * 128;
    const int lRow  = tid >> 1;
    const int lCol  = (tid & 1) * 4;
    const int tx    = tid & 15;
    const int ty    = tid >> 4;

    const float4* Ap = (const float4*)(A + (size_t)(vBase + lRow) * H_N + lCol);
    const float4* Wp = (const float4*)(W + (size_t)(hBase + lRow) * H_N + lCol);

    float acc[8][8];
#pragma unroll
    for (int i = 0; i < 8; i++)
#pragma unroll
        for (int j = 0; j < 8; j++) acc[i][j] = 0.f;

    float4 av = Ap[0];
    float4 wv = Wp[0];

    for (int k0 = 0; k0 < 512; k0 += 8) {
        __syncthreads();
        As[lCol + 0][lRow] = av.x; As[lCol + 1][lRow] = av.y;
        As[lCol + 2][lRow] = av.z; As[lCol + 3][lRow] = av.w;
        Ws[lCol + 0][lRow] = wv.x; Ws[lCol + 1][lRow] = wv.y;
        Ws[lCol + 2][lRow] = wv.z; Ws[lCol + 3][lRow] = wv.w;
        __syncthreads();
        if (k0 + 8 < 512) {
            av = Ap[(k0 + 8) >> 2];
            wv = Wp[(k0 + 8) >> 2];
        }
#pragma unroll
        for (int k = 0; k < 8; k++) {
            float a[8], w[8];
            *(float4*)&a[0] = *(const float4*)&As[k][ty * 8];
            *(float4*)&a[4] = *(const float4*)&As[k][ty * 8 + 4];
            *(float4*)&w[0] = *(const float4*)&Ws[k][tx * 8];
            *(float4*)&w[4] = *(const float4*)&Ws[k][tx * 8 + 4];
#pragma unroll
            for (int i = 0; i < 8; i++)
#pragma unroll
                for (int j = 0; j < 8; j++) acc[i][j] += a[i] * w[j];
        }
    }

#pragma unroll
    for (int i = 0; i < 8; i++) {
        const int v = vBase + ty * 8 + i;
        float* orow = &g_embW0[(size_t)v * H_N + hBase + tx * 8];
        float o[8];
#pragma unroll
        for (int j = 0; j < 8; j++) {
            int h = hBase + tx * 8 + j;
            o[j] = acc[i][j] + __ldg(&bih[h]) + __ldg(&bhh[h]);
        }
        *(float4*)&orow[0] = *(float4*)&o[0];
        *(float4*)&orow[4] = *(float4*)&o[4];
    }
}

// ---------------- packed-fp32 helpers ----------------
typedef unsigned long long u64;
__device__ __forceinline__ u64 ffma2(u64 a, u64 b, u64 c) {
    u64 d;
    asm("fma.rn.f32x2 %0, %1, %2, %3;" : "=l"(d) : "l"(a), "l"(b), "l"(c));
    return d;
}
__device__ __forceinline__ float unpack_sum(u64 a) {
    float lo, hi;
    asm("mov.b64 {%0, %1}, %2;" : "=f"(lo), "=f"(hi) : "l"(a));
    return lo + hi;
}

// ---------------- persistent recurrence kernel (batch-grouped) ----------------
// SMEM floats: W0[8192] WA[8192] WB[8192] Hs0[8192] Hs1[8192] Rs0[4352] Rs1[4352] b1[16]
#define OFF_W0 0
#define OFF_WA 8192
#define OFF_WB 16384
#define OFF_H0 24576
#define OFF_H1 32768
#define OFF_R0 40960
#define OFF_R1 (OFF_R0 + 4352)
#define OFF_B1 (OFF_R1 + 4352)
#define SMEM_FLOATS (OFF_B1 + 16)
#define SMEM_BYTES  (SMEM_FLOATS * 4)

__global__ __launch_bounds__(NTHR, 1) void rnn_kernel(const int*   __restrict__ input,
                                                      const float* __restrict__ Whh0,
                                                      const float* __restrict__ Wih1,
                                                      const float* __restrict__ Whh1,
                                                      const float* __restrict__ bih1,
                                                      const float* __restrict__ bhh1,
                                                      float*       __restrict__ out) {
    extern __shared__ float smem[];
    float* W0s = smem + OFF_W0;
    float* WAs = smem + OFF_WA;
    float* WBs = smem + OFF_WB;
    float* Hs0 = smem + OFF_H0;
    float* Hs1 = smem + OFF_H1;
    float* Rs0 = smem + OFF_R0;
    float* Rs1 = smem + OFF_R1;
    float* b1s = smem + OFF_B1;

    const int tid  = threadIdx.x;
    const int cid  = blockIdx.x;
    const int m    = cid & (GC - 1);   // member: cols [m*16, m*16+16)
    const int grp  = cid >> 5;         // group: batches [grp*16, grp*16+16)
    const int gb16 = grp * BPG;
    const int w    = tid >> 5;
    const int lane = tid & 31;
    const int o    = w >> 2;           // batch-oct (0..1)
    const int cc   = w & 3;            // col-quad  (0..3)

    // ---- preload weight slices: rows [m*16, m*16+16) ----
    {
        const float4* s0 = (const float4*)Whh0 + (size_t)m * 2048;
        const float4* s1 = (const float4*)Wih1 + (size_t)m * 2048;
        const float4* s2 = (const float4*)Whh1 + (size_t)m * 2048;
        float4* d0 = (float4*)W0s; float4* d1 = (float4*)WAs; float4* d2 = (float4*)WBs;
        for (int r = tid; r < 2048; r += NTHR) {
            d0[r] = __ldg(&s0[r]);
            d1[r] = __ldg(&s1[r]);
            d2[r] = __ldg(&s2[r]);
        }
        if (tid < CPM) b1s[tid] = __ldg(&bih1[m * CPM + tid]) + __ldg(&bhh1[m * CPM + tid]);
    }
    __syncthreads();

    // output decode: thread tid owns Rs row tid
    const int w_o    = tid >> 5;
    const int i_o    = (tid >> 2) & 7;
    const int c_o    = tid & 3;
    const int b_out  = gb16 + (w_o >> 2) * 8 + i_o;
    const int c_loc  = (w_o & 3) * 4 + c_o;
    const int c_glob = m * CPM + c_loc;

    const ulonglong2* W0u = (const ulonglong2*)W0s;
    const ulonglong2* WAu = (const ulonglong2*)WAs;
    const ulonglong2* WBu = (const ulonglong2*)WBs;
    const ulonglong2* H0u = (const ulonglong2*)Hs0;
    const ulonglong2* H1u = (const ulonglong2*)Hs1;
    const unsigned sd0 = (unsigned)__cvta_generic_to_shared(Hs0);
    const unsigned sd1 = (unsigned)__cvta_generic_to_shared(Hs1);

    u64 acc0[8][4], accA[8][4];

    // fused pass-1 chunk: one k-quarter J; hv shared across both weight sets
#define MMA1_CHUNK(J)                                                            \
    {                                                                            \
        ulonglong2 w0q[4], waq[4];                                               \
        _Pragma("unroll")                                                        \
        for (int c = 0; c < 4; c++) {                                            \
            int row = cc * 4 + c;                                                \
            w0q[c] = W0u[row * 128 + (J) * 32 + lane];                           \
            waq[c] = WAu[row * 128 + (J) * 32 + lane];                           \
        }                                                                        \
        _Pragma("unroll")                                                        \
        for (int i = 0; i < 8; i++) {                                            \
            ulonglong2 hv = H0u[(J) * 512 + (o * 8 + i) * 32 + lane];            \
            _Pragma("unroll")                                                    \
            for (int c = 0; c < 4; c++) {                                        \
                acc0[i][c] = ffma2(hv.x, w0q[c].x, acc0[i][c]);                  \
                acc0[i][c] = ffma2(hv.y, w0q[c].y, acc0[i][c]);                  \
                accA[i][c] = ffma2(hv.x, waq[c].x, accA[i][c]);                  \
                accA[i][c] = ffma2(hv.y, waq[c].y, accA[i][c]);                  \
            }                                                                    \
        }                                                                        \
    }

    // pass-2 chunk: Whh1 · h1[s-3] accumulated into accA
#define MMA2_CHUNK(J)                                                            \
    {                                                                            \
        ulonglong2 wbq[4];                                                       \
        _Pragma("unroll")                                                        \
        for (int c = 0; c < 4; c++)                                              \
            wbq[c] = WBu[(cc * 4 + c) * 128 + (J) * 32 + lane];                  \
        _Pragma("unroll")                                                        \
        for (int i = 0; i < 8; i++) {                                            \
            ulonglong2 hv = H1u[(J) * 512 + (o * 8 + i) * 32 + lane];            \
            _Pragma("unroll")                                                    \
            for (int c = 0; c < 4; c++) {                                        \
                accA[i][c] = ffma2(hv.x, wbq[c].x, accA[i][c]);                  \
                accA[i][c] = ffma2(hv.y, wbq[c].y, accA[i][c]);                  \
            }                                                                    \
        }                                                                        \
    }

    // shfl pre-reduce ACC -> RS (lanes 0..15 write rows of 16, stride 17)
#define REDUCE_TO(RS, ACC)                                                       \
    _Pragma("unroll")                                                            \
    for (int i = 0; i < 8; i++)                                                  \
        _Pragma("unroll")                                                        \
        for (int c = 0; c < 4; c++) {                                            \
            float v = unpack_sum(ACC[i][c]);                                     \
            v += __shfl_xor_sync(0xffffffffu, v, 16);                            \
            if (lane < 16) (RS)[(w * 32 + i * 4 + c) * 17 + lane] = v;           \
        }

    for (int s = 1; s <= T_N + 1; s++) {
        const bool doH0 = (s <= T_N);
        const bool doH1 = (s >= 2);

        // ---- gather input-projection value early ----
        float xw = 0.f;
        if (doH0) {
            int tok = __ldg(&input[(s - 1) * B_N + b_out]);
            xw = __ldcg(&g_embW0[(size_t)tok * H_N + c_glob]);
        }

        // ---- stage group's h0[s-2], h1[s-3]: 4 mixed commit groups ----
        {
            const float* h0src = g_h0[s & 1];
            const float* h1src = g_h1[(s + 1) & 1];
#pragma unroll
            for (int j = 0; j < 4; j++) {
#pragma unroll
                for (int m2 = 0; m2 < 2; m2++) {
                    int l   = m2 * NTHR + tid;         // 0..511
                    int b_l = l >> 5;
                    int c4  = l & 31;
                    size_t srcf4 = (size_t)(gb16 + b_l) * 128 + j * 32 + c4;
                    asm volatile("cp.async.cg.shared.global [%0], [%1], 16;\n"
                                 :: "r"(sd0 + (j * 512 + l) * 16), "l"(h0src + srcf4 * 4));
                    asm volatile("cp.async.cg.shared.global [%0], [%1], 16;\n"
                                 :: "r"(sd1 + (j * 512 + l) * 16), "l"(h1src + srcf4 * 4));
                }
                asm volatile("cp.async.commit_group;\n");
            }
        }

#pragma unroll
        for (int i = 0; i < 8; i++)
#pragma unroll
            for (int c = 0; c < 4; c++) { acc0[i][c] = 0ull; accA[i][c] = 0ull; }

        // ---- pass 1 (fused Whh0 + Wih1 on h0[s-2]) ----
        asm volatile("cp.async.wait_group 3;\n" ::: "memory");
        __syncthreads();
        MMA1_CHUNK(0)
        asm volatile("cp.async.wait_group 2;\n" ::: "memory");
        __syncthreads();
        MMA1_CHUNK(1)
        asm volatile("cp.async.wait_group 1;\n" ::: "memory");
        __syncthreads();
        MMA1_CHUNK(2)
        asm volatile("cp.async.wait_group 0;\n" ::: "memory");
        __syncthreads();
        MMA1_CHUNK(3)

        // ---- reduce0 + h0 store (L2 latency hides behind pass 2) ----
        REDUCE_TO(Rs0, acc0)
        __syncthreads();
        if (doH0) {
            float ssum = 0.f;
#pragma unroll
            for (int l = 0; l < 16; l++) ssum += Rs0[tid * 17 + l];
            __stcg(&g_h0[(s - 1) & 1][b_out * H_N + c_glob], tanhf(ssum + xw));
        }

        // ---- pass 2 (Whh1 on h1[s-3]); all data already visible ----
        MMA2_CHUNK(0)
        MMA2_CHUNK(1)
        MMA2_CHUNK(2)
        MMA2_CHUNK(3)

        // ---- reduce1 + h1 store ----
        REDUCE_TO(Rs1, accA)
        __syncthreads();
        if (doH1) {
            float ssum = 0.f;
#pragma unroll
            for (int l = 0; l < 16; l++) ssum += Rs1[tid * 17 + l];
            float v = tanhf(ssum + b1s[c_loc]);
            __stcg(&g_h1[s & 1][b_out * H_N + c_glob], v);
            if (s == T_N + 1) __stcg(&out[b_out * H_N + c_glob], v);
        }

        // ---- group barrier: 32 members, flag-based ----
        __syncthreads();
        if (tid == 0) {
            __threadfence();
            asm volatile("st.relaxed.gpu.global.u32 [%0], %1;"
                         :: "l"(&g_flag[cid * 8]), "r"((unsigned)s) : "memory");
        }
        if (w == 0) {
            const unsigned* fp = &g_flag[(grp * GC + lane) * 8];
            unsigned v;
            do {
                asm volatile("ld.relaxed.gpu.global.u32 %0, [%1];"
                             : "=r"(v) : "l"(fp) : "memory");
            } while (__any_sync(0xffffffffu, v < (unsigned)s));
            __threadfence();
        }
        __syncthreads();
    }
#undef MMA1_CHUNK
#undef MMA2_CHUNK
#undef REDUCE_TO
}

// ---------------- launch ----------------
extern "C" void kernel_launch(void* const* d_in, const int* in_sizes, int n_in,
                              void* d_out, int out_size) {
    const int*   input = (const int*)  d_in[0];
    const float* emb   = (const float*)d_in[1];
    const float* Wih0  = (const float*)d_in[2];
    const float* Whh0  = (const float*)d_in[3];
    const float* bih0  = (const float*)d_in[4];
    const float* bhh0  = (const float*)d_in[5];
    const float* Wih1  = (const float*)d_in[6];
    const float* Whh1  = (const float*)d_in[7];
    const float* bih1  = (const float*)d_in[8];
    const float* bhh1  = (const float*)d_in[9];
    float* out = (float*)d_out;

    cudaFuncSetAttribute(rnn_kernel, cudaFuncAttributeMaxDynamicSharedMemorySize, SMEM_BYTES);

    reset_kernel<<<(B_N * H_N + 255) / 256, 256>>>();
    embw_kernel<<<dim3(H_N / 128, V_N / 128), 256>>>(emb, Wih0, bih0, bhh0);
    rnn_kernel<<<GRID_R, NTHR, SMEM_BYTES>>>(input, Whh0, Wih1, Whh1, bih1, bhh1, out);
}